// round 9
// baseline (speedup 1.0000x reference)
#include <cuda_runtime.h>

#define B 256
#define NFULL 100
#define R 80
#define D4 192             // 768 / 4 floats -> one float4 per thread per row
#define THRESH 0.5f
#define JCHUNK 4           // slots per block -> 8 independent loads per thread
#define GRIDX (R / JCHUNK) // 20

// Index of the (j+1)-th set bit across the 80-bit mask (u0,u1,u2).
__device__ __forceinline__ int nth_set(unsigned u0, unsigned u1, unsigned u2,
                                       int c0, int c1, int j)
{
    if (j < c0)       return (int)__fns(u0, 0, j + 1);
    j -= c0;
    if (j < c1)       return 32 + (int)__fns(u1, 0, j + 1);
    j -= c1;
    return 64 + (int)__fns(u2, 0, j + 1);
}

// ---------------------------------------------------------------------------
// Grid (20, 256), 192 threads. Barrier-free per-warp ballot meta, then each
// thread streams 4 slots x (vis+txt): 8 independent 16B loads issued before
// any store (max MLP), 8 coalesced streaming stores. Block (0,b) emits the
// small metadata outputs. All address math in int32.
// ---------------------------------------------------------------------------
__global__ void fused_kernel(const float4* __restrict__ vis,      // (B,100,192)
                             const float4* __restrict__ txt,      // (B,100,192)
                             const float*  __restrict__ rr_in,    // (B,100)
                             const float*  __restrict__ labels_in,// (B,100)
                             float4* __restrict__ vis_out,        // (B,80,192)
                             float4* __restrict__ txt_out,        // (B,80,192)
                             float*  __restrict__ text_mask,      // (B,81)
                             float*  __restrict__ img_mask,       // (B,81)
                             float*  __restrict__ rr_mod,         // (B,80)
                             float*  __restrict__ labels_out)     // (B,80)
{
    const int b  = blockIdx.y;           // 0..255
    const int t  = threadIdx.x;          // 0..191
    const int l  = t & 31;               // lane
    const int w  = t >> 5;               // warp (0..5)
    const int j0 = blockIdx.x * JCHUNK;  // first slot this block owns

    // Per-warp mask build: 3 loads (L2-resident) + 3 ballots. No smem/barrier.
    const float* rrow = rr_in + b * NFULL;
    const float ra = rrow[l];
    const float rb = rrow[32 + l];
    const float rc = rrow[64 + l];       // 95 < 100: in-bounds; masked below

    const unsigned u0 =  __ballot_sync(0xffffffffu, ra > THRESH);
    const unsigned u1 =  __ballot_sync(0xffffffffu, rb > THRESH);
    const unsigned u2 = (__ballot_sync(0xffffffffu, rc > THRESH)) & 0xFFFFu;

    const int c0 = __popc(u0), c1 = __popc(u1), c2 = __popc(u2);
    const int cnt = c0 + c1 + c2;

    // Metadata outputs: one block per batch (tiny traffic).
    if (blockIdx.x == 0) {
        const unsigned g0 =  __ballot_sync(0xffffffffu, ra >= THRESH);
        const unsigned g1 =  __ballot_sync(0xffffffffu, rb >= THRESH);
        const unsigned g2 = (__ballot_sync(0xffffffffu, rc >= THRESH)) & 0xFFFFu;
        if (t < R) {
            const float rv = (w == 0) ? ra : (w == 1) ? rb : rc;  // rr[t]
            float rm = (rv < THRESH) ? 0.0f : rv;        // rr==0.5 survives
            if (t == 0 && (g0 | g1 | g2) == 0u)
                rm = 1.0f;                               // zero-row fixup
            rr_mod[b * R + t]     = rm;
            labels_out[b * R + t] = labels_in[b * NFULL + t];
        }
        if (t <= R) {  // 81 entries
            float tm = (t <= cnt) ? 1.0f : 0.0f;
            text_mask[b * (R + 1) + t] = tm;
            img_mask [b * (R + 1) + t] = (b == B - 1) ? tm : 1.0f;
        }
    }

    // Heavy streaming. Load phase: up to 8 independent LDG.128 in flight.
    const float4 z = make_float4(0.0f, 0.0f, 0.0f, 0.0f);
    float4 v[JCHUNK], x[JCHUNK];
    int    out_off[JCHUNK];

    #pragma unroll
    for (int jj = 0; jj < JCHUNK; jj++) {
        const int j = j0 + jj;
        out_off[jj] = (b * R + j) * D4 + t;              // < 2^22, int-safe
        if (j < cnt) {
            const int src = nth_set(u0, u1, u2, c0, c1, j);
            const int in_off = (b * NFULL + src) * D4 + t;
            v[jj] = vis[in_off];
            x[jj] = txt[in_off];
        } else {
            v[jj] = z;
            x[jj] = z;
        }
    }

    // Store phase: 8 coalesced streaming stores (output never re-read).
    #pragma unroll
    for (int jj = 0; jj < JCHUNK; jj++) {
        __stcs(vis_out + out_off[jj], v[jj]);
        __stcs(txt_out + out_off[jj], x[jj]);
    }
}

// ---------------------------------------------------------------------------
// Inputs (metadata order):
//   0: mean_pooling_vec (unused)   1: merge_text_vec (unused)
//   2: retrieved_visual_feature_embedding_cls (B,100,1,768)
//   3: retrieved_textual_feature_embedding   (B,100,1,768)
//   4: retrieved_label_list (B,100)          5: RRCP (B,100)
// Output (concatenated f32):
//   vis_packed (B,80,768) | txt_packed (B,80,768) | text_mask (B,81)
//   | img_mask (B,81) | rr_mod (B,80) | labels (B,80)
// ---------------------------------------------------------------------------
extern "C" void kernel_launch(void* const* d_in, const int* in_sizes, int n_in,
                              void* d_out, int out_size)
{
    const float* vis    = (const float*)d_in[2];
    const float* txt    = (const float*)d_in[3];
    const float* labels = (const float*)d_in[4];
    const float* rr     = (const float*)d_in[5];

    float* out = (float*)d_out;
    const long VIS_SZ  = (long)B * R * 768;     // 15,728,640
    const long MASK_SZ = (long)B * (R + 1);     // 20,736
    const long ROW_SZ  = (long)B * R;           // 20,480

    float* vis_out   = out;
    float* txt_out   = out + VIS_SZ;
    float* text_mask = out + 2 * VIS_SZ;
    float* img_mask  = text_mask + MASK_SZ;
    float* rr_mod    = img_mask + MASK_SZ;
    float* labels_o  = rr_mod + ROW_SZ;

    dim3 grid(GRIDX, B);
    fused_kernel<<<grid, D4>>>((const float4*)vis, (const float4*)txt,
                               rr, labels,
                               (float4*)vis_out, (float4*)txt_out,
                               text_mask, img_mask, rr_mod, labels_o);
}

// round 10
// speedup vs baseline: 1.0019x; 1.0019x over previous
#include <cuda_runtime.h>

#define B 256
#define NFULL 100
#define R 80
#define D4 192             // 768 / 4 floats -> one float4 per thread per row
#define THRESH 0.5f
#define JCHUNK 2           // slots per block (best-measured: occ 77%, 27.8us)
#define GRIDX (R / JCHUNK) // 40

// Index of the (j+1)-th set bit across the 80-bit mask (u0,u1,u2).
// Caller guarantees j < popc(u0)+popc(u1)+popc(u2).
__device__ __forceinline__ int nth_set(unsigned u0, unsigned u1, unsigned u2,
                                       int c0, int c1, int j)
{
    if (j < c0)       return (int)__fns(u0, 0, j + 1);
    j -= c0;
    if (j < c1)       return 32 + (int)__fns(u1, 0, j + 1);
    j -= c1;
    return 64 + (int)__fns(u2, 0, j + 1);
}

// ---------------------------------------------------------------------------
// Grid (40, 256), 192 threads. Barrier-free meta: each warp independently
// loads the batch's 80 RRCP values (L2-resident) and derives the 80-bit keep
// mask via 3 ballots — no smem, no __syncthreads. Each thread then streams
// 2 slots x (vis+txt): 4 independent 16B loads, 4 coalesced streaming stores.
// Block (0,b) additionally emits the small metadata outputs.
// All heavy-path address math in int32 (offsets < 2^22).
// ---------------------------------------------------------------------------
__global__ void fused_kernel(const float4* __restrict__ vis,      // (B,100,192)
                             const float4* __restrict__ txt,      // (B,100,192)
                             const float*  __restrict__ rr_in,    // (B,100)
                             const float*  __restrict__ labels_in,// (B,100)
                             float4* __restrict__ vis_out,        // (B,80,192)
                             float4* __restrict__ txt_out,        // (B,80,192)
                             float*  __restrict__ text_mask,      // (B,81)
                             float*  __restrict__ img_mask,       // (B,81)
                             float*  __restrict__ rr_mod,         // (B,80)
                             float*  __restrict__ labels_out)     // (B,80)
{
    const int b  = blockIdx.y;           // 0..255
    const int t  = threadIdx.x;          // 0..191
    const int l  = t & 31;               // lane
    const int w  = t >> 5;               // warp (0..5)
    const int j0 = blockIdx.x * JCHUNK;  // first slot this block owns

    // Per-warp mask build: 3 loads (L2-resident after first wave) + 3 ballots.
    const float* rrow = rr_in + b * NFULL;
    const float ra = rrow[l];
    const float rb = rrow[32 + l];
    const float rc = rrow[64 + l];       // 95 < 100: in-bounds; masked below

    const unsigned u0 =  __ballot_sync(0xffffffffu, ra > THRESH);
    const unsigned u1 =  __ballot_sync(0xffffffffu, rb > THRESH);
    const unsigned u2 = (__ballot_sync(0xffffffffu, rc > THRESH)) & 0xFFFFu;

    const int c0 = __popc(u0), c1 = __popc(u1), c2 = __popc(u2);
    const int cnt = c0 + c1 + c2;

    // Metadata outputs: one block per batch (tiny traffic).
    if (blockIdx.x == 0) {
        const unsigned g0 =  __ballot_sync(0xffffffffu, ra >= THRESH);
        const unsigned g1 =  __ballot_sync(0xffffffffu, rb >= THRESH);
        const unsigned g2 = (__ballot_sync(0xffffffffu, rc >= THRESH)) & 0xFFFFu;
        if (t < R) {
            const float rv = (w == 0) ? ra : (w == 1) ? rb : rc;  // rr[t]
            float rm = (rv < THRESH) ? 0.0f : rv;        // rr==0.5 survives
            if (t == 0 && (g0 | g1 | g2) == 0u)
                rm = 1.0f;                               // zero-row fixup
            rr_mod[b * R + t]     = rm;
            labels_out[b * R + t] = labels_in[b * NFULL + t];
        }
        if (t <= R) {  // 81 entries
            float tm = (t <= cnt) ? 1.0f : 0.0f;
            text_mask[b * (R + 1) + t] = tm;
            img_mask [b * (R + 1) + t] = (b == B - 1) ? tm : 1.0f;
        }
    }

    // Heavy streaming: 2 slots, 4 independent loads then 4 streaming stores.
    const int  jA   = j0;
    const int  jB   = j0 + 1;
    const int  outA = (b * R + jA) * D4 + t;             // int32-safe (< 2^22)
    const int  outB = (b * R + jB) * D4 + t;
    const float4 z  = make_float4(0.0f, 0.0f, 0.0f, 0.0f);

    float4 va = z, xa = z, vb = z, xb = z;
    if (jA < cnt) {
        const int srcA = nth_set(u0, u1, u2, c0, c1, jA);
        const int inA  = (b * NFULL + srcA) * D4 + t;
        va = vis[inA];
        xa = txt[inA];
    }
    if (jB < cnt) {
        const int srcB = nth_set(u0, u1, u2, c0, c1, jB);
        const int inB  = (b * NFULL + srcB) * D4 + t;
        vb = vis[inB];
        xb = txt[inB];
    }
    __stcs(vis_out + outA, va);
    __stcs(txt_out + outA, xa);
    __stcs(vis_out + outB, vb);
    __stcs(txt_out + outB, xb);
}

// ---------------------------------------------------------------------------
// Inputs (metadata order):
//   0: mean_pooling_vec (unused)   1: merge_text_vec (unused)
//   2: retrieved_visual_feature_embedding_cls (B,100,1,768)
//   3: retrieved_textual_feature_embedding   (B,100,1,768)
//   4: retrieved_label_list (B,100)          5: RRCP (B,100)
// Output (concatenated f32):
//   vis_packed (B,80,768) | txt_packed (B,80,768) | text_mask (B,81)
//   | img_mask (B,81) | rr_mod (B,80) | labels (B,80)
// ---------------------------------------------------------------------------
extern "C" void kernel_launch(void* const* d_in, const int* in_sizes, int n_in,
                              void* d_out, int out_size)
{
    const float* vis    = (const float*)d_in[2];
    const float* txt    = (const float*)d_in[3];
    const float* labels = (const float*)d_in[4];
    const float* rr     = (const float*)d_in[5];

    float* out = (float*)d_out;
    const long VIS_SZ  = (long)B * R * 768;     // 15,728,640
    const long MASK_SZ = (long)B * (R + 1);     // 20,736
    const long ROW_SZ  = (long)B * R;           // 20,480

    float* vis_out   = out;
    float* txt_out   = out + VIS_SZ;
    float* text_mask = out + 2 * VIS_SZ;
    float* img_mask  = text_mask + MASK_SZ;
    float* rr_mod    = img_mask + MASK_SZ;
    float* labels_o  = rr_mod + ROW_SZ;

    dim3 grid(GRIDX, B);
    fused_kernel<<<grid, D4>>>((const float4*)vis, (const float4*)txt,
                               rr, labels,
                               (float4*)vis_out, (float4*)txt_out,
                               text_mask, img_mask, rr_mod, labels_o);
}